// round 5
// baseline (speedup 1.0000x reference)
#include <cuda_runtime.h>

// FSRS-3 recurrence: SEQ=64 steps, BATCH=262144 independent columns.
// inputs: (SEQ, BATCH, 2) f32 interleaved [t, rating]; w: (13,) f32.
// out: outputs (SEQ, BATCH, 2) [s, d] followed by final_state (BATCH, 2).
// Each thread owns 2 adjacent columns -> float4 (16B) coalesced ld/st and
// two independent dependency chains to hide MUFU latency.

#define SEQ   64
#define BATCH 262144
#define COLS2 (BATCH / 2)          // float4 groups per step
#define OUT_MAIN (SEQ * BATCH * 2) // floats in outputs block

// Single-instruction MUFU ops via PTX (guaranteed, independent of fast-math flags)
__device__ __forceinline__ float fast_ex2(float x) {
    float y;
    asm("ex2.approx.ftz.f32 %0, %1;" : "=f"(y) : "f"(x));
    return y;
}
__device__ __forceinline__ float fast_lg2(float x) {
    float y;
    asm("lg2.approx.ftz.f32 %0, %1;" : "=f"(y) : "f"(x));
    return y;
}
__device__ __forceinline__ float fast_rcp(float x) {
    float y;
    asm("rcp.approx.ftz.f32 %0, %1;" : "=f"(y) : "f"(x));
    return y;
}

__device__ __forceinline__ float clip_s(float x) {
    return fminf(fmaxf(x, 0.1f), 36500.0f);
}
__device__ __forceinline__ float clip_d(float x) {
    return fminf(fmaxf(x, 1.0f), 10.0f);
}

// log2(0.9)
#define LOG2_09 (-0.15200309344504997f)
// log2(e)
#define LOG2_E  (1.4426950408889634f)

struct Consts {
    float w2w5;   // w5*w2
    float om_w5;  // 1-w5
    float w4, w7, w9, w10, w11;
    float ew6;    // exp(w6)
    float w8l2;   // w8*log2(e)
    float w12l2;  // w12*log2(e)
};

__device__ __forceinline__ void fsrs_step(float t, float rating,
                                          float& s, float& d,
                                          const Consts& c) {
    // r = 0.9^(t/s) = exp2(log2(0.9) * t * (1/s))
    float ratio = t * fast_rcp(s);
    float r = fast_ex2(LOG2_09 * ratio);
    float new_d = clip_d(c.w2w5 + c.om_w5 * (d + c.w4 * (rating - 3.0f)));
    float lgs = fast_lg2(s);
    float s_w7  = fast_ex2(c.w7  * lgs);
    float s_w11 = fast_ex2(c.w11 * lgs);
    float omr = 1.0f - r;
    // succ = s*(1 + e^w6 * (11-new_d) * s^w7 * (exp(omr*w8)-1))
    float succ = s * (1.0f + c.ew6 * (11.0f - new_d) * s_w7 *
                             (fast_ex2(omr * c.w8l2) - 1.0f));
    // fail = w9 * new_d^w10 * s^w11 * exp(omr*w12)
    float fail = c.w9 * fast_ex2(c.w10 * fast_lg2(new_d)) * s_w11 *
                 fast_ex2(omr * c.w12l2);
    s = clip_s(rating > 1.0f ? succ : fail);
    d = new_d;
}

__global__ void __launch_bounds__(256)
fsrs3_kernel(const float* __restrict__ in, const float* __restrict__ w,
             float* __restrict__ out, int write_final) {
    int g = blockIdx.x * blockDim.x + threadIdx.x;  // float4-group index
    if (g >= COLS2) return;

    // Broadcast weight loads (uniform across warp -> cheap)
    float w0 = w[0],  w1 = w[1],  w2 = w[2],  w3 = w[3],  w4 = w[4];
    float w5 = w[5],  w6 = w[6],  w7 = w[7],  w8 = w[8],  w9 = w[9];
    float w10 = w[10], w11 = w[11], w12 = w[12];

    Consts c;
    c.w2w5  = w5 * w2;
    c.om_w5 = 1.0f - w5;
    c.w4 = w4; c.w7 = w7; c.w9 = w9; c.w10 = w10; c.w11 = w11;
    c.ew6   = fast_ex2(w6 * LOG2_E);
    c.w8l2  = w8 * LOG2_E;
    c.w12l2 = w12 * LOG2_E;

    const float4* inp  = (const float4*)in;   // (SEQ, COLS2)
    float4*       outp = (float4*)out;        // (SEQ, COLS2)

    // ---- first step (step 0) ----
    float4 X = inp[g];   // {t_a, rating_a, t_b, rating_b}
    float sa = clip_s(w0 + w1 * (X.y - 1.0f));
    float da = clip_d(w2 + w3 * (X.y - 3.0f));
    float sb = clip_s(w0 + w1 * (X.w - 1.0f));
    float db = clip_d(w2 + w3 * (X.w - 3.0f));
    outp[g] = make_float4(sa, da, sb, db);

    // software prefetch of the next step's tile
    float4 Xn = inp[COLS2 + g];

    // steps 1 .. SEQ-2 (prefetch next tile each iteration, branch-free)
    #pragma unroll 1
    for (int step = 1; step < SEQ - 1; ++step) {
        X = Xn;
        Xn = inp[(step + 1) * COLS2 + g];
        fsrs_step(X.x, X.y, sa, da, c);
        fsrs_step(X.z, X.w, sb, db, c);
        outp[step * COLS2 + g] = make_float4(sa, da, sb, db);
    }

    // peeled last step (SEQ-1): no prefetch, then final_state write
    fsrs_step(Xn.x, Xn.y, sa, da, c);
    fsrs_step(Xn.z, Xn.w, sb, db, c);
    float4 last = make_float4(sa, da, sb, db);
    outp[(SEQ - 1) * COLS2 + g] = last;

    if (write_final) {
        ((float4*)(out + OUT_MAIN))[g] = last;
    }
}

extern "C" void kernel_launch(void* const* d_in, const int* in_sizes, int n_in,
                              void* d_out, int out_size) {
    const float* in = (const float*)d_in[0];   // inputs (SEQ, BATCH, 2)
    const float* w  = (const float*)d_in[1];   // w (13,)
    float* out = (float*)d_out;

    int write_final = (out_size >= OUT_MAIN + 2 * BATCH) ? 1 : 0;

    int threads = 256;
    int blocks  = (COLS2 + threads - 1) / threads;  // 512
    fsrs3_kernel<<<blocks, threads>>>(in, w, out, write_final);
}

// round 7
// speedup vs baseline: 1.1164x; 1.1164x over previous
#include <cuda_runtime.h>

// FSRS-3 recurrence: SEQ=64 steps, BATCH=262144 independent columns.
// R6: 1 column/thread (262144 threads) to double occupancy (40%->~85%);
// MUFU count reduced 9->7 per step via exponent fusion.
// inputs: (SEQ, BATCH, 2) f32 [t, rating]; out: (SEQ, BATCH, 2) [s,d] + final (BATCH,2).

#define SEQ   64
#define BATCH 262144
#define OUT_MAIN (SEQ * BATCH * 2) // floats in outputs block

__device__ __forceinline__ float fast_ex2(float x) {
    float y; asm("ex2.approx.ftz.f32 %0, %1;" : "=f"(y) : "f"(x)); return y;
}
__device__ __forceinline__ float fast_lg2(float x) {
    float y; asm("lg2.approx.ftz.f32 %0, %1;" : "=f"(y) : "f"(x)); return y;
}
__device__ __forceinline__ float fast_rcp(float x) {
    float y; asm("rcp.approx.ftz.f32 %0, %1;" : "=f"(y) : "f"(x)); return y;
}

__device__ __forceinline__ float clip_s(float x) {
    return fminf(fmaxf(x, 0.1f), 36500.0f);
}
__device__ __forceinline__ float clip_d(float x) {
    return fminf(fmaxf(x, 1.0f), 10.0f);
}

#define LOG2_09 (-0.15200309344504997f)  // log2(0.9)
#define LOG2_E  (1.4426950408889634f)    // log2(e)

struct Consts {
    float w2w5;    // w5*w2
    float om_w5;   // 1-w5
    float w4, w7, w10, w11;
    float w6l2;    // w6*log2(e)  (so e^w6 * s^w7 = ex2(w6l2 + w7*lgs))
    float w8l2;    // w8*log2(e)
    float w12l2;   // w12*log2(e)
    float w9;
};

__device__ __forceinline__ void fsrs_step(float t, float rating,
                                          float& s, float& d,
                                          const Consts& c) {
    // r = 0.9^(t/s)
    float ratio = t * fast_rcp(s);                     // MUFU 1 (rcp)
    float r = fast_ex2(LOG2_09 * ratio);               // MUFU 2 (ex2)
    float new_d = clip_d(c.w2w5 + c.om_w5 * (d + c.w4 * (rating - 3.0f)));
    float lgs = fast_lg2(s);                           // MUFU 3 (lg2)
    float omr = 1.0f - r;
    // succ = s * (1 + ex2(w6l2 + w7*lgs) * (11-new_d) * (ex2(omr*w8l2) - 1))
    float spow = fast_ex2(fmaf(c.w7, lgs, c.w6l2));    // MUFU 4 (ex2)
    float egrow = fast_ex2(omr * c.w8l2) - 1.0f;       // MUFU 5 (ex2)
    float succ = s * fmaf(spow * (11.0f - new_d), egrow, 1.0f);
    // fail = w9 * ex2(w10*lg2(new_d) + w11*lgs + omr*w12l2)   (fused: one ex2)
    float lgd = fast_lg2(new_d);                       // MUFU 6 (lg2)
    float fexp = fmaf(c.w10, lgd, fmaf(c.w11, lgs, omr * c.w12l2));
    float fail = c.w9 * fast_ex2(fexp);                // MUFU 7 (ex2)
    s = clip_s(rating > 1.0f ? succ : fail);
    d = new_d;
}

__global__ void __launch_bounds__(256)
fsrs3_kernel(const float* __restrict__ in, const float* __restrict__ w,
             float* __restrict__ out, int write_final) {
    int g = blockIdx.x * blockDim.x + threadIdx.x;  // column index
    if (g >= BATCH) return;

    float w0 = w[0],  w1 = w[1],  w2 = w[2],  w3 = w[3],  w4 = w[4];
    float w5 = w[5],  w6 = w[6],  w7 = w[7],  w8 = w[8],  w9 = w[9];
    float w10 = w[10], w11 = w[11], w12 = w[12];

    Consts c;
    c.w2w5  = w5 * w2;
    c.om_w5 = 1.0f - w5;
    c.w4 = w4; c.w7 = w7; c.w10 = w10; c.w11 = w11; c.w9 = w9;
    c.w6l2  = w6  * LOG2_E;
    c.w8l2  = w8  * LOG2_E;
    c.w12l2 = w12 * LOG2_E;

    const float2* inp  = (const float2*)in;   // (SEQ, BATCH) of {t, rating}
    float2*       outp = (float2*)out;        // (SEQ, BATCH) of {s, d}

    // ---- step 0 ----
    float2 X = inp[g];
    float s = clip_s(fmaf(w1, X.y - 1.0f, w0));
    float d = clip_d(fmaf(w3, X.y - 3.0f, w2));
    outp[g] = make_float2(s, d);

    // prefetch next step
    float2 Xn = inp[BATCH + g];

    #pragma unroll 1
    for (int step = 1; step < SEQ - 1; ++step) {
        X = Xn;
        Xn = inp[(step + 1) * BATCH + g];
        fsrs_step(X.x, X.y, s, d, c);
        outp[step * BATCH + g] = make_float2(s, d);
    }

    // peeled last step + final_state
    fsrs_step(Xn.x, Xn.y, s, d, c);
    float2 last = make_float2(s, d);
    outp[(SEQ - 1) * BATCH + g] = last;

    if (write_final) {
        ((float2*)(out + OUT_MAIN))[g] = last;
    }
}

extern "C" void kernel_launch(void* const* d_in, const int* in_sizes, int n_in,
                              void* d_out, int out_size) {
    const float* in = (const float*)d_in[0];   // inputs (SEQ, BATCH, 2)
    const float* w  = (const float*)d_in[1];   // w (13,)
    float* out = (float*)d_out;

    int write_final = (out_size >= OUT_MAIN + 2 * BATCH) ? 1 : 0;

    int threads = 256;
    int blocks  = BATCH / threads;  // 1024
    fsrs3_kernel<<<blocks, threads>>>(in, w, out, write_final);
}

// round 8
// speedup vs baseline: 1.1492x; 1.0294x over previous
#include <cuda_runtime.h>

// FSRS-3 recurrence: SEQ=64 steps, BATCH=262144 independent columns.
// R8: MUFU 7->6 via predicated ex2 merge; prefetch depth 2; streaming
// cache hints (__ldcs/__stcs); 128-thread blocks for smoother occupancy.

#define SEQ   64
#define BATCH 262144
#define OUT_MAIN (SEQ * BATCH * 2) // floats in outputs block

__device__ __forceinline__ float fast_ex2(float x) {
    float y; asm("ex2.approx.ftz.f32 %0, %1;" : "=f"(y) : "f"(x)); return y;
}
__device__ __forceinline__ float fast_lg2(float x) {
    float y; asm("lg2.approx.ftz.f32 %0, %1;" : "=f"(y) : "f"(x)); return y;
}
__device__ __forceinline__ float fast_rcp(float x) {
    float y; asm("rcp.approx.ftz.f32 %0, %1;" : "=f"(y) : "f"(x)); return y;
}

__device__ __forceinline__ float clip_s(float x) {
    return fminf(fmaxf(x, 0.1f), 36500.0f);
}
__device__ __forceinline__ float clip_d(float x) {
    return fminf(fmaxf(x, 1.0f), 10.0f);
}

#define LOG2_09 (-0.15200309344504997f)  // log2(0.9)
#define LOG2_E  (1.4426950408889634f)    // log2(e)

struct Consts {
    float w2w5;    // w5*w2
    float om_w5;   // 1-w5
    float w4, w7, w10, w11;
    float w6l2;    // w6*log2(e)
    float w8l2;    // w8*log2(e)
    float w12l2;   // w12*log2(e)
    float w9;
};

__device__ __forceinline__ void fsrs_step(float t, float rating,
                                          float& s, float& d,
                                          const Consts& c) {
    // 6 MUFU per step: rcp, ex2(r), lg2(s), lg2(d'), ex2(main), ex2(egrow)
    float ratio = t * fast_rcp(s);                         // MUFU 1
    float r = fast_ex2(LOG2_09 * ratio);                   // MUFU 2
    float new_d = clip_d(c.w2w5 + c.om_w5 * (d + c.w4 * (rating - 3.0f)));
    float lgs = fast_lg2(s);                               // MUFU 3
    float omr = 1.0f - r;
    bool p = rating > 1.0f;

    float lgd = fast_lg2(new_d);                           // MUFU 4 (fail path; new_d>=1 safe)
    // merged exponent: succ -> w6l2 + w7*lgs ; fail -> w10*lgd + w11*lgs + omr*w12l2
    float e_succ = fmaf(c.w7, lgs, c.w6l2);
    float e_fail = fmaf(c.w10, lgd, fmaf(c.w11, lgs, omr * c.w12l2));
    float e_main = fast_ex2(p ? e_succ : e_fail);          // MUFU 5
    float egrow = fast_ex2(omr * c.w8l2) - 1.0f;           // MUFU 6 (succ only)

    float succ = s * fmaf(e_main * (11.0f - new_d), egrow, 1.0f);
    float fail = c.w9 * e_main;
    s = clip_s(p ? succ : fail);
    d = new_d;
}

__global__ void __launch_bounds__(128)
fsrs3_kernel(const float* __restrict__ in, const float* __restrict__ w,
             float* __restrict__ out, int write_final) {
    int g = blockIdx.x * blockDim.x + threadIdx.x;  // column index
    if (g >= BATCH) return;

    float w0 = w[0],  w1 = w[1],  w2 = w[2],  w3 = w[3],  w4 = w[4];
    float w5 = w[5],  w6 = w[6],  w7 = w[7],  w8 = w[8],  w9 = w[9];
    float w10 = w[10], w11 = w[11], w12 = w[12];

    Consts c;
    c.w2w5  = w5 * w2;
    c.om_w5 = 1.0f - w5;
    c.w4 = w4; c.w7 = w7; c.w10 = w10; c.w11 = w11; c.w9 = w9;
    c.w6l2  = w6  * LOG2_E;
    c.w8l2  = w8  * LOG2_E;
    c.w12l2 = w12 * LOG2_E;

    const float2* inp  = (const float2*)in;   // (SEQ, BATCH) of {t, rating}
    float2*       outp = (float2*)out;        // (SEQ, BATCH) of {s, d}

    // ---- step 0 ----
    float2 X0 = __ldcs(&inp[g]);
    float s = clip_s(fmaf(w1, X0.y - 1.0f, w0));
    float d = clip_d(fmaf(w3, X0.y - 3.0f, w2));
    __stcs(&outp[g], make_float2(s, d));

    // prefetch two steps ahead (MLP = 2)
    float2 Xa = __ldcs(&inp[BATCH + g]);          // step 1 data
    float2 Xb = __ldcs(&inp[2 * BATCH + g]);      // step 2 data

    #pragma unroll 1
    for (int step = 1; step < SEQ - 2; ++step) {
        float2 X = Xa;
        Xa = Xb;
        Xb = __ldcs(&inp[(step + 2) * BATCH + g]);
        fsrs_step(X.x, X.y, s, d, c);
        __stcs(&outp[step * BATCH + g], make_float2(s, d));
    }

    // step SEQ-2 (data in Xa)
    fsrs_step(Xa.x, Xa.y, s, d, c);
    __stcs(&outp[(SEQ - 2) * BATCH + g], make_float2(s, d));

    // step SEQ-1 (data in Xb) + final_state
    fsrs_step(Xb.x, Xb.y, s, d, c);
    float2 last = make_float2(s, d);
    __stcs(&outp[(SEQ - 1) * BATCH + g], last);

    if (write_final) {
        __stcs(&((float2*)(out + OUT_MAIN))[g], last);
    }
}

extern "C" void kernel_launch(void* const* d_in, const int* in_sizes, int n_in,
                              void* d_out, int out_size) {
    const float* in = (const float*)d_in[0];   // inputs (SEQ, BATCH, 2)
    const float* w  = (const float*)d_in[1];   // w (13,)
    float* out = (float*)d_out;

    int write_final = (out_size >= OUT_MAIN + 2 * BATCH) ? 1 : 0;

    int threads = 128;
    int blocks  = BATCH / threads;  // 2048
    fsrs3_kernel<<<blocks, threads>>>(in, w, out, write_final);
}